// round 3
// baseline (speedup 1.0000x reference)
#include <cuda_runtime.h>

// Problem: x (2,128,512,512) f32.
//   edge = sum_o |conv(sum_c x, sobel_o)|  (channel-independent)
//   out  = maxpool2x2(edge) broadcast to (2,128,256,256)
//
// K1: channel half-sums (reads 256MB) -> g_part[2][2][512*512] (4 MB)
//     (channel dim split in two so total warps double -> higher occ, more MLP)
// K2: per (pooled row, 32-channel group): sum partials, sobel x4 + abs-sum
//     + maxpool -> smem row, then broadcast-write 32 channels (writes 64MB,
//     L2-absorbed)

#define S_SPATIAL   (512 * 512)       // 262144
#define S_SPATIAL4  (S_SPATIAL / 4)   // 65536
#define NCH         128
#define NB          2

__device__ float g_part[2 * NB * S_SPATIAL];    // 4 MB scratch: [half][b][spatial]

// ---------------- K1: channel half-sum (float4) ----------------
__global__ void __launch_bounds__(256) k_chansum(const float4* __restrict__ x) {
    int idx = blockIdx.x * blockDim.x + threadIdx.x;   // 0 .. 262143
    if (idx >= 2 * NB * S_SPATIAL4) return;
    int h  = idx >> 17;              // channel half 0/1
    int r  = idx & 0x1FFFF;
    int b  = r >> 16;
    int sp = r & 0xFFFF;
    const float4* p = x + ((size_t)b * NCH + (size_t)h * (NCH / 2)) * S_SPATIAL4 + sp;
    float4 acc = make_float4(0.f, 0.f, 0.f, 0.f);
#pragma unroll 16
    for (int c = 0; c < NCH / 2; c++) {
        float4 v = p[(size_t)c * S_SPATIAL4];
        acc.x += v.x; acc.y += v.y; acc.z += v.z; acc.w += v.w;
    }
    // layout: [(h*2 + b)][sp4]
    ((float4*)g_part)[((h * NB + b) << 16) + sp] = acc;
}

// ---------------- K2 fused: edge+pool row -> broadcast 32 channels ----------------
__device__ __forceinline__ float edge_at(const float p[4][4], int dy, int dx) {
    float a = p[dy][dx],     bb = p[dy][dx+1],   c = p[dy][dx+2];
    float d = p[dy+1][dx],                        f = p[dy+1][dx+2];
    float g = p[dy+2][dx],   h = p[dy+2][dx+1],  i = p[dy+2][dx+2];
    // XLA conv = cross-correlation (no kernel flip)
    float e0 = -a + c - 2.f*d + 2.f*f - g + i;
    float e1 =  a + 2.f*bb + c - g - 2.f*h - i;
    float e2 =  2.f*a + bb + d - f - h - 2.f*i;
    float e3 = -bb - 2.f*c + d - f + 2.f*g + h;
    return fabsf(e0) + fabsf(e1) + fabsf(e2) + fabsf(e3);
}

__global__ void __launch_bounds__(256) k_edgecast(float4* __restrict__ out) {
    // grid = NB * 256 * 4 = 2048 blocks. block = (b, py, channel-group cg of 32)
    int cg = blockIdx.x & 3;
    int py = (blockIdx.x >> 2) & 255;
    int b  = blockIdx.x >> 10;
    int tid = threadIdx.x;           // = px, 0..255

    __shared__ float row[256];       // pooled edge row
    {
        const float* s0 = g_part + (0 * NB + b) * S_SPATIAL;
        const float* s1 = g_part + (1 * NB + b) * S_SPATIAL;
        int y0 = 2 * py - 1, x0 = 2 * tid - 1;
        float patch[4][4];
#pragma unroll
        for (int r = 0; r < 4; r++) {
            int y = y0 + r;
            bool yok = (y >= 0) & (y < 512);
#pragma unroll
            for (int cx = 0; cx < 4; cx++) {
                int xx = x0 + cx;
                bool ok = yok & (xx >= 0) & (xx < 512);
                int off = y * 512 + xx;
                patch[r][cx] = ok ? (__ldg(s0 + off) + __ldg(s1 + off)) : 0.f;
            }
        }
        row[tid] = fmaxf(fmaxf(edge_at(patch, 0, 0), edge_at(patch, 0, 1)),
                         fmaxf(edge_at(patch, 1, 0), edge_at(patch, 1, 1)));
    }
    __syncthreads();

    // Broadcast write: 32 channels x 64 float4 per row = 2048 float4 / block.
    // Each iter: 256 threads write 4 channels' worth, fully coalesced.
    int px4  = tid & 63;             // float4 index within row
    int csub = tid >> 6;             // 0..3
    float4 v = ((const float4*)row)[px4];
    int c0 = cg * 32 + csub;
    // out index for (b, c, py, px4): ((b*128 + c)*256 + py)*64 + px4
    float4* o = out + ((size_t)(b * NCH + c0) * 256 + py) * 64 + px4;
#pragma unroll
    for (int i = 0; i < 8; i++) {
        *o = v;
        o += (size_t)4 * 256 * 64;   // advance 4 channels
    }
}

extern "C" void kernel_launch(void* const* d_in, const int* in_sizes, int n_in,
                              void* d_out, int out_size) {
    const float4* x = (const float4*)d_in[0];
    float4* out = (float4*)d_out;

    k_chansum<<<(2 * NB * S_SPATIAL4 + 255) / 256, 256>>>(x);
    k_edgecast<<<NB * 256 * 4, 256>>>(out);
}